// round 2
// baseline (speedup 1.0000x reference)
#include <cuda_runtime.h>

#define BQ    16384
#define DIN   1024
#define DOUT  1024
#define HDIM  2048
#define NE    8
#define NA    (BQ*2)
#define PADM  33792          /* 264 tiles of 128; >= 32768 + 8*127 */
#define MTILES (PADM/128)

/* ---------------- scratch (__device__ globals: no allocation allowed) ------ */
__device__ float g_h[PADM * HDIM];          /* 276 MB intermediate h */
__device__ int   g_tok[PADM];
__device__ float g_wgt[PADM];
__device__ int   g_counts[NE];
__device__ int   g_cnt2[NE];
__device__ int   g_segbase[NE + 1];
__device__ int   g_tope[NA];
__device__ float g_topw[NA];
__device__ float g_probs_scratch[BQ * NE];

/* ---------------- packed f32x2 helpers (FFMA2: 2x FFMA throughput) -------- */
__device__ __forceinline__ unsigned long long fma2(unsigned long long a,
                                                   unsigned long long b,
                                                   unsigned long long c) {
    unsigned long long d;
    asm("fma.rn.f32x2 %0, %1, %2, %3;" : "=l"(d) : "l"(a), "l"(b), "l"(c));
    return d;
}
__device__ __forceinline__ unsigned long long dup2(float x) {
    unsigned long long d;
    asm("mov.b64 %0, {%1, %1};" : "=l"(d) : "f"(x));
    return d;
}
__device__ __forceinline__ float2 unpk2(unsigned long long v) {
    float2 r;
    asm("mov.b64 {%0, %1}, %2;" : "=f"(r.x), "=f"(r.y) : "l"(v));
    return r;
}

/* ---------------- init ----------------------------------------------------- */
__global__ void k_zero_out(float* __restrict__ out) {
    size_t i = (size_t)blockIdx.x * blockDim.x + threadIdx.x;   /* 4194304 float4 */
    ((float4*)out)[i] = make_float4(0.f, 0.f, 0.f, 0.f);
}

__global__ void k_init() {
    int tid = threadIdx.x;
    if (tid < NE) { g_counts[tid] = 0; g_cnt2[tid] = 0; }
    for (int i = tid; i < PADM; i += blockDim.x) g_tok[i] = -1;
}

/* ---------------- router: logits -> softmax -> top2 ------------------------ */
__global__ void k_router(const float* __restrict__ x,
                         const float* __restrict__ rW,
                         const float* __restrict__ rb,
                         float* __restrict__ probs_out) {
    const int b = blockIdx.x;
    const int tid = threadIdx.x;              /* 128 threads */
    const float* xr = x + (size_t)b * DIN;

    float acc[NE];
#pragma unroll
    for (int e = 0; e < NE; e++) acc[e] = 0.f;
    for (int k = tid; k < DIN; k += 128) {
        float xv = xr[k];
#pragma unroll
        for (int e = 0; e < NE; e++) acc[e] = fmaf(xv, rW[e * DIN + k], acc[e]);
    }
    __shared__ float red[NE][128];
#pragma unroll
    for (int e = 0; e < NE; e++) red[e][tid] = acc[e];
    __syncthreads();
    for (int s = 64; s > 0; s >>= 1) {
        if (tid < s) {
#pragma unroll
            for (int e = 0; e < NE; e++) red[e][tid] += red[e][tid + s];
        }
        __syncthreads();
    }
    if (tid == 0) {
        float lg[NE], mx = -1e30f;
#pragma unroll
        for (int e = 0; e < NE; e++) { lg[e] = red[e][0] + rb[e]; mx = fmaxf(mx, lg[e]); }
        float p[NE], s = 0.f;
#pragma unroll
        for (int e = 0; e < NE; e++) { p[e] = expf(lg[e] - mx); s += p[e]; }
        float inv = 1.f / s;
#pragma unroll
        for (int e = 0; e < NE; e++) { p[e] *= inv; probs_out[(size_t)b * NE + e] = p[e]; }
        int i0 = 0;
#pragma unroll
        for (int e = 1; e < NE; e++) if (p[e] > p[i0]) i0 = e;
        int i1 = (i0 == 0) ? 1 : 0;
#pragma unroll
        for (int e = 0; e < NE; e++) if (e != i0 && p[e] > p[i1]) i1 = e;
        float ws = p[i0] + p[i1];
        g_tope[2 * b]     = i0; g_topw[2 * b]     = p[i0] / ws;
        g_tope[2 * b + 1] = i1; g_topw[2 * b + 1] = p[i1] / ws;
        atomicAdd(&g_counts[i0], 1);
        atomicAdd(&g_counts[i1], 1);
    }
}

/* ---------------- prefix & scatter into padded expert segments ------------- */
__global__ void k_prefix() {
    int base = 0;
    for (int e = 0; e < NE; e++) {
        g_segbase[e] = base;
        base += ((g_counts[e] + 127) >> 7) << 7;
    }
    g_segbase[NE] = base;
}

__global__ void k_scatter() {
    int a = blockIdx.x * 256 + threadIdx.x;
    if (a < NA) {
        int e = g_tope[a];
        int pos = g_segbase[e] + atomicAdd(&g_cnt2[e], 1);
        g_tok[pos] = a >> 1;
        g_wgt[pos] = g_topw[a];
    }
}

/* ---------------- GEMM1: h = relu(X_gather @ W1_e^T + b1_e) ---------------- */
__global__ __launch_bounds__(256, 2)
void k_gemm1(const float* __restrict__ x,
             const float* __restrict__ W1,
             const float* __restrict__ b1) {
    __shared__ float As[16][132];
    __shared__ float Bs[16][132];
    __shared__ int   stok[128];
    __shared__ int   s_e;

    const int tid = threadIdx.x;
    const int p0 = blockIdx.y * 128;
    const int n0 = blockIdx.x * 128;

    if (tid == 0) {
        int e = -1;
        if (p0 < g_segbase[NE]) {
#pragma unroll
            for (int i = NE - 1; i >= 0; i--)
                if (p0 >= g_segbase[i]) { e = i; break; }
        }
        s_e = e;
    }
    if (tid < 128) stok[tid] = g_tok[p0 + tid];
    __syncthreads();
    const int e = s_e;
    if (e < 0) return;

    const float* Bp = W1 + (size_t)e * HDIM * DIN + (size_t)n0 * DIN;
    const int tx = tid & 15, ty = tid >> 4;
    const int r0 = tid >> 2, c0 = (tid & 3) * 4;

    const int t0 = stok[r0], t1 = stok[r0 + 64];
    const bool v0 = (t0 >= 0), v1 = (t1 >= 0);
    const float* ap0 = v0 ? (x + (size_t)t0 * DIN + c0) : x;
    const float* ap1 = v1 ? (x + (size_t)t1 * DIN + c0) : x;
    const float* bp0 = Bp + (size_t)r0 * DIN + c0;
    const float* bp1 = Bp + (size_t)(r0 + 64) * DIN + c0;

    unsigned long long accp[8][4];
#pragma unroll
    for (int i = 0; i < 8; i++)
#pragma unroll
        for (int j = 0; j < 4; j++) accp[i][j] = 0ull;

    for (int kk = 0; kk < DIN; kk += 16) {
        float4 za = make_float4(0.f, 0.f, 0.f, 0.f);
        float4 av0 = v0 ? *(const float4*)(ap0 + kk) : za;
        float4 av1 = v1 ? *(const float4*)(ap1 + kk) : za;
        float4 bv0 = *(const float4*)(bp0 + kk);
        float4 bv1 = *(const float4*)(bp1 + kk);
        __syncthreads();
        As[c0 + 0][r0] = av0.x; As[c0 + 1][r0] = av0.y; As[c0 + 2][r0] = av0.z; As[c0 + 3][r0] = av0.w;
        As[c0 + 0][r0 + 64] = av1.x; As[c0 + 1][r0 + 64] = av1.y; As[c0 + 2][r0 + 64] = av1.z; As[c0 + 3][r0 + 64] = av1.w;
        Bs[c0 + 0][r0] = bv0.x; Bs[c0 + 1][r0] = bv0.y; Bs[c0 + 2][r0] = bv0.z; Bs[c0 + 3][r0] = bv0.w;
        Bs[c0 + 0][r0 + 64] = bv1.x; Bs[c0 + 1][r0 + 64] = bv1.y; Bs[c0 + 2][r0 + 64] = bv1.z; Bs[c0 + 3][r0 + 64] = bv1.w;
        __syncthreads();
#pragma unroll
        for (int k = 0; k < 16; k++) {
            float4 a0 = *(const float4*)&As[k][ty * 8];
            float4 a1 = *(const float4*)&As[k][ty * 8 + 4];
            ulonglong2 bL = *(const ulonglong2*)&Bs[k][tx * 8];
            ulonglong2 bH = *(const ulonglong2*)&Bs[k][tx * 8 + 4];
#define ROWFMA(i, aval) { unsigned long long ad = dup2(aval);               \
            accp[i][0] = fma2(ad, bL.x, accp[i][0]);                        \
            accp[i][1] = fma2(ad, bL.y, accp[i][1]);                        \
            accp[i][2] = fma2(ad, bH.x, accp[i][2]);                        \
            accp[i][3] = fma2(ad, bH.y, accp[i][3]); }
            ROWFMA(0, a0.x) ROWFMA(1, a0.y) ROWFMA(2, a0.z) ROWFMA(3, a0.w)
            ROWFMA(4, a1.x) ROWFMA(5, a1.y) ROWFMA(6, a1.z) ROWFMA(7, a1.w)
#undef ROWFMA
        }
    }

    const float* b1p = b1 + (size_t)e * HDIM + n0 + tx * 8;
    float4 bb0 = *(const float4*)b1p;
    float4 bb1 = *(const float4*)(b1p + 4);
    float bias[8] = {bb0.x, bb0.y, bb0.z, bb0.w, bb1.x, bb1.y, bb1.z, bb1.w};
#pragma unroll
    for (int i = 0; i < 8; i++) {
        float r[8];
#pragma unroll
        for (int jp = 0; jp < 4; jp++) {
            float2 v = unpk2(accp[i][jp]);
            r[2 * jp]     = fmaxf(v.x + bias[2 * jp], 0.f);
            r[2 * jp + 1] = fmaxf(v.y + bias[2 * jp + 1], 0.f);
        }
        float* dst = &g_h[(size_t)(p0 + ty * 8 + i) * HDIM + n0 + tx * 8];
        *(float4*)dst       = make_float4(r[0], r[1], r[2], r[3]);
        *(float4*)(dst + 4) = make_float4(r[4], r[5], r[6], r[7]);
    }
}

/* ---------------- GEMM2: out += w * (h @ W2_e^T + b2_e) -------------------- */
__global__ __launch_bounds__(256, 2)
void k_gemm2(const float* __restrict__ W2,
             const float* __restrict__ b2,
             float* __restrict__ out) {
    __shared__ float As[16][132];
    __shared__ float Bs[16][132];
    __shared__ int   stok[128];
    __shared__ float swgt[128];
    __shared__ int   s_e;

    const int tid = threadIdx.x;
    const int p0 = blockIdx.y * 128;
    const int n0 = blockIdx.x * 128;

    if (tid == 0) {
        int e = -1;
        if (p0 < g_segbase[NE]) {
#pragma unroll
            for (int i = NE - 1; i >= 0; i--)
                if (p0 >= g_segbase[i]) { e = i; break; }
        }
        s_e = e;
    }
    if (tid < 128) { stok[tid] = g_tok[p0 + tid]; swgt[tid] = g_wgt[p0 + tid]; }
    __syncthreads();
    const int e = s_e;
    if (e < 0) return;

    const float* Bp = W2 + (size_t)e * DOUT * HDIM + (size_t)n0 * HDIM;
    const int tx = tid & 15, ty = tid >> 4;
    const int r0 = tid >> 2, c0 = (tid & 3) * 4;

    const float* ap0 = g_h + (size_t)(p0 + r0) * HDIM + c0;
    const float* ap1 = g_h + (size_t)(p0 + r0 + 64) * HDIM + c0;
    const float* bp0 = Bp + (size_t)r0 * HDIM + c0;
    const float* bp1 = Bp + (size_t)(r0 + 64) * HDIM + c0;

    unsigned long long accp[8][4];
#pragma unroll
    for (int i = 0; i < 8; i++)
#pragma unroll
        for (int j = 0; j < 4; j++) accp[i][j] = 0ull;

    for (int kk = 0; kk < HDIM; kk += 16) {
        float4 av0 = *(const float4*)(ap0 + kk);
        float4 av1 = *(const float4*)(ap1 + kk);
        float4 bv0 = *(const float4*)(bp0 + kk);
        float4 bv1 = *(const float4*)(bp1 + kk);
        __syncthreads();
        As[c0 + 0][r0] = av0.x; As[c0 + 1][r0] = av0.y; As[c0 + 2][r0] = av0.z; As[c0 + 3][r0] = av0.w;
        As[c0 + 0][r0 + 64] = av1.x; As[c0 + 1][r0 + 64] = av1.y; As[c0 + 2][r0 + 64] = av1.z; As[c0 + 3][r0 + 64] = av1.w;
        Bs[c0 + 0][r0] = bv0.x; Bs[c0 + 1][r0] = bv0.y; Bs[c0 + 2][r0] = bv0.z; Bs[c0 + 3][r0] = bv0.w;
        Bs[c0 + 0][r0 + 64] = bv1.x; Bs[c0 + 1][r0 + 64] = bv1.y; Bs[c0 + 2][r0 + 64] = bv1.z; Bs[c0 + 3][r0 + 64] = bv1.w;
        __syncthreads();
#pragma unroll
        for (int k = 0; k < 16; k++) {
            float4 a0 = *(const float4*)&As[k][ty * 8];
            float4 a1 = *(const float4*)&As[k][ty * 8 + 4];
            ulonglong2 bL = *(const ulonglong2*)&Bs[k][tx * 8];
            ulonglong2 bH = *(const ulonglong2*)&Bs[k][tx * 8 + 4];
#define ROWFMA(i, aval) { unsigned long long ad = dup2(aval);               \
            accp[i][0] = fma2(ad, bL.x, accp[i][0]);                        \
            accp[i][1] = fma2(ad, bL.y, accp[i][1]);                        \
            accp[i][2] = fma2(ad, bH.x, accp[i][2]);                        \
            accp[i][3] = fma2(ad, bH.y, accp[i][3]); }
            ROWFMA(0, a0.x) ROWFMA(1, a0.y) ROWFMA(2, a0.z) ROWFMA(3, a0.w)
            ROWFMA(4, a1.x) ROWFMA(5, a1.y) ROWFMA(6, a1.z) ROWFMA(7, a1.w)
#undef ROWFMA
        }
    }

    const float* b2p = b2 + (size_t)e * DOUT + n0 + tx * 8;
    float4 bb0 = *(const float4*)b2p;
    float4 bb1 = *(const float4*)(b2p + 4);
    float bias[8] = {bb0.x, bb0.y, bb0.z, bb0.w, bb1.x, bb1.y, bb1.z, bb1.w};
#pragma unroll
    for (int i = 0; i < 8; i++) {
        int row = ty * 8 + i;
        int t = stok[row];
        if (t < 0) continue;
        float w = swgt[row];
        float* dst = out + (size_t)t * DOUT + n0 + tx * 8;
#pragma unroll
        for (int jp = 0; jp < 4; jp++) {
            float2 v = unpk2(accp[i][jp]);
            atomicAdd(dst + 2 * jp,     w * (v.x + bias[2 * jp]));
            atomicAdd(dst + 2 * jp + 1, w * (v.y + bias[2 * jp + 1]));
        }
    }
}

/* ---------------- launch ---------------------------------------------------- */
extern "C" void kernel_launch(void* const* d_in, const int* in_sizes, int n_in,
                              void* d_out, int out_size) {
    const float* x   = (const float*)d_in[0];
    const float* rW  = (const float*)d_in[1];
    const float* rb  = (const float*)d_in[2];
    const float* W1  = (const float*)d_in[3];
    const float* b1  = (const float*)d_in[4];
    const float* W2  = (const float*)d_in[5];
    const float* b2  = (const float*)d_in[6];
    float* out = (float*)d_out;

    /* router_probs are the second output (flattened after out[B, DOUT]) */
    float* probs;
    if (out_size >= (int)(BQ * DOUT + BQ * NE)) {
        probs = out + (size_t)BQ * DOUT;
    } else {
        void* p = nullptr;
        cudaGetSymbolAddress(&p, g_probs_scratch);
        probs = (float*)p;
    }

    k_zero_out<<<16384, 256>>>(out);           /* zero out[B, DOUT] */
    k_init<<<1, 256>>>();
    k_router<<<BQ, 128>>>(x, rW, rb, probs);
    k_prefix<<<1, 1>>>();
    k_scatter<<<NA / 256, 256>>>();
    dim3 g1(HDIM / 128, MTILES);
    k_gemm1<<<g1, 256>>>(x, W1, b1);
    dim3 g2(DOUT / 128, MTILES);
    k_gemm2<<<g2, 256>>>(W2, b2, out);
    (void)in_sizes; (void)n_in;
}

// round 6
// speedup vs baseline: 2.5269x; 2.5269x over previous
#include <cuda_runtime.h>
#include <cuda_bf16.h>

#define BQ    16384
#define DIN   1024
#define DOUT  1024
#define HDIM  2048
#define NE    8
#define NA    (BQ*2)
#define PADM  35072              /* segments padded to 256: 137 blocks of 256 */
#define MT    137
#define KB1   (DIN/32)           /* 32 */
#define KB2   (HDIM/32)          /* 64 */
#define NT1   (HDIM/128)         /* 16 */
#define NT2   (DOUT/128)         /* 8  */
#define STAGE_UINTS 12288        /* 48KB: Ah 4096 | Al 4096 | Bh 2048 | Bl 2048 */
#define DSMEM_BYTES (4*STAGE_UINTS*4)   /* 196608 */

/* ---------------- scratch: bf16 fragment-blocked buffers ------------------- */
/* A-layout block (256 rows x 32 cols) = 4096 uints:                           */
/*   [ki(2)][mi(16)][lane(32)][4 regs]  (reg = packed bf16x2)                  */
/* B-layout block (128 rows x 32 cols) = 2048 uints:                           */
/*   [ki(2)][ni(16)][lane(32)][2 regs]                                         */
__device__ unsigned g_xh[(size_t)PADM * DIN / 2];
__device__ unsigned g_xl[(size_t)PADM * DIN / 2];
__device__ unsigned g_w1h[(size_t)NE * HDIM * DIN / 2];
__device__ unsigned g_w1l[(size_t)NE * HDIM * DIN / 2];
__device__ unsigned g_w2h[(size_t)NE * DOUT * HDIM / 2];
__device__ unsigned g_w2l[(size_t)NE * DOUT * HDIM / 2];
__device__ unsigned g_hh[(size_t)PADM * HDIM / 2];
__device__ unsigned g_hl[(size_t)PADM * HDIM / 2];
__device__ int   g_tok[PADM];
__device__ float g_wgt[PADM];
__device__ int   g_counts[NE];
__device__ int   g_cnt2[NE];
__device__ int   g_segbase[NE + 1];
__device__ int   g_tope[NA];
__device__ float g_topw[NA];
__device__ float g_probs_scratch[BQ * NE];

/* ---------------- PTX helpers --------------------------------------------- */
__device__ __forceinline__ unsigned smem_u32(const void* p) {
    unsigned a;
    asm("{ .reg .u64 t; cvta.to.shared.u64 t, %1; cvt.u32.u64 %0, t; }" : "=r"(a) : "l"(p));
    return a;
}
#define CP16(dst, src) \
    asm volatile("cp.async.cg.shared.global [%0], [%1], 16;" :: "r"(dst), "l"(src) : "memory")
#define CP_COMMIT() asm volatile("cp.async.commit_group;" ::: "memory")

__device__ __forceinline__ void mma16816(float* c, const uint4 a, const uint2 b) {
    asm("mma.sync.aligned.m16n8k16.row.col.f32.bf16.bf16.f32 "
        "{%0,%1,%2,%3}, {%4,%5,%6,%7}, {%8,%9}, {%0,%1,%2,%3};"
        : "+f"(c[0]), "+f"(c[1]), "+f"(c[2]), "+f"(c[3])
        : "r"(a.x), "r"(a.y), "r"(a.z), "r"(a.w), "r"(b.x), "r"(b.y));
}

/* split two floats into packed bf16x2 hi and lo parts */
__device__ __forceinline__ void bsplit2(float a, float b, unsigned& hi, unsigned& lo) {
    __nv_bfloat162 h = __floats2bfloat162_rn(a, b);
    float ra = a - __bfloat162float(h.x);
    float rb = b - __bfloat162float(h.y);
    __nv_bfloat162 l = __floats2bfloat162_rn(ra, rb);
    hi = *reinterpret_cast<unsigned*>(&h);
    lo = *reinterpret_cast<unsigned*>(&l);
}

/* ---------------- init ----------------------------------------------------- */
__global__ void k_zero_out(float* __restrict__ out) {
    size_t i = (size_t)blockIdx.x * blockDim.x + threadIdx.x;
    ((float4*)out)[i] = make_float4(0.f, 0.f, 0.f, 0.f);
}
__global__ void k_init() {
    int tid = threadIdx.x;
    if (tid < NE) { g_counts[tid] = 0; g_cnt2[tid] = 0; }
    for (int i = tid; i < PADM; i += blockDim.x) g_tok[i] = -1;
}

/* ---------------- router --------------------------------------------------- */
__global__ void k_router(const float* __restrict__ x,
                         const float* __restrict__ rW,
                         const float* __restrict__ rb,
                         float* __restrict__ probs_out) {
    const int b = blockIdx.x;
    const int tid = threadIdx.x;
    const float* xr = x + (size_t)b * DIN;
    float acc[NE];
#pragma unroll
    for (int e = 0; e < NE; e++) acc[e] = 0.f;
    for (int k = tid; k < DIN; k += 128) {
        float xv = xr[k];
#pragma unroll
        for (int e = 0; e < NE; e++) acc[e] = fmaf(xv, rW[e * DIN + k], acc[e]);
    }
    __shared__ float red[NE][128];
#pragma unroll
    for (int e = 0; e < NE; e++) red[e][tid] = acc[e];
    __syncthreads();
    for (int s = 64; s > 0; s >>= 1) {
        if (tid < s) {
#pragma unroll
            for (int e = 0; e < NE; e++) red[e][tid] += red[e][tid + s];
        }
        __syncthreads();
    }
    if (tid == 0) {
        float lg[NE], mx = -1e30f;
#pragma unroll
        for (int e = 0; e < NE; e++) { lg[e] = red[e][0] + rb[e]; mx = fmaxf(mx, lg[e]); }
        float p[NE], s = 0.f;
#pragma unroll
        for (int e = 0; e < NE; e++) { p[e] = expf(lg[e] - mx); s += p[e]; }
        float inv = 1.f / s;
#pragma unroll
        for (int e = 0; e < NE; e++) { p[e] *= inv; probs_out[(size_t)b * NE + e] = p[e]; }
        int i0 = 0;
#pragma unroll
        for (int e = 1; e < NE; e++) if (p[e] > p[i0]) i0 = e;
        int i1 = (i0 == 0) ? 1 : 0;
#pragma unroll
        for (int e = 0; e < NE; e++) if (e != i0 && p[e] > p[i1]) i1 = e;
        float ws = p[i0] + p[i1];
        g_tope[2 * b]     = i0; g_topw[2 * b]     = p[i0] / ws;
        g_tope[2 * b + 1] = i1; g_topw[2 * b + 1] = p[i1] / ws;
        atomicAdd(&g_counts[i0], 1);
        atomicAdd(&g_counts[i1], 1);
    }
}

__global__ void k_prefix() {
    int base = 0;
    for (int e = 0; e < NE; e++) {
        g_segbase[e] = base;
        base += ((g_counts[e] + 255) >> 8) << 8;
    }
    g_segbase[NE] = base;
}
__global__ void k_scatter() {
    int a = blockIdx.x * 256 + threadIdx.x;
    if (a < NA) {
        int e = g_tope[a];
        int pos = g_segbase[e] + atomicAdd(&g_cnt2[e], 1);
        g_tok[pos] = a >> 1;
        g_wgt[pos] = g_topw[a];
    }
}

/* ---------------- x: gather + split into A-layout -------------------------- */
__global__ void k_xsplit(const float* __restrict__ x) {
    const int kb = blockIdx.x, mb = blockIdx.y;
    const int tid = threadIdx.x;                 /* 512 */
    const int lane = tid & 31, mi = tid >> 5;
    const int g = lane >> 2, tig = lane & 3;
    const int row0 = mb * 256 + mi * 16 + g;
    const int t0 = g_tok[row0], t1 = g_tok[row0 + 8];
    const size_t blk = ((size_t)mb * KB1 + kb) * 4096;
#pragma unroll
    for (int ki = 0; ki < 2; ki++) {
        const int col = kb * 32 + ki * 16 + 2 * tig;
        float2 z = make_float2(0.f, 0.f);
        float2 v00 = z, v01 = z, v10 = z, v11 = z;
        if (t0 >= 0) {
            v00 = *(const float2*)&x[(size_t)t0 * DIN + col];
            v01 = *(const float2*)&x[(size_t)t0 * DIN + col + 8];
        }
        if (t1 >= 0) {
            v10 = *(const float2*)&x[(size_t)t1 * DIN + col];
            v11 = *(const float2*)&x[(size_t)t1 * DIN + col + 8];
        }
        uint4 hi, lo;
        bsplit2(v00.x, v00.y, hi.x, lo.x);   /* a0: (g,   c..c+1)   */
        bsplit2(v10.x, v10.y, hi.y, lo.y);   /* a1: (g+8, c..c+1)   */
        bsplit2(v01.x, v01.y, hi.z, lo.z);   /* a2: (g,   c+8..c+9) */
        bsplit2(v11.x, v11.y, hi.w, lo.w);   /* a3: (g+8, c+8..c+9) */
        const size_t base = blk + ((size_t)(ki * 16 + mi) * 32 + lane) * 4;
        *(uint4*)&g_xh[base] = hi;
        *(uint4*)&g_xl[base] = lo;
    }
}

/* ---------------- W split into B-layout ------------------------------------ */
/* Gh/Gl must be DEVICE addresses resolved via cudaGetSymbolAddress on host!  */
__global__ void k_wsplit(const float* __restrict__ W,
                         unsigned* __restrict__ Gh, unsigned* __restrict__ Gl,
                         int Kdim) {
    const int kb = blockIdx.x, nt = blockIdx.y, e = blockIdx.z;
    const int NB = gridDim.y;
    const int tid = threadIdx.x;                 /* 512 */
    const int lane = tid & 31, ni = tid >> 5;
    const int g = lane >> 2, tig = lane & 3;
    const size_t nrow = (size_t)e * (NB * 128) + nt * 128 + ni * 8 + g;
    const float* src = W + nrow * Kdim + kb * 32;
    const size_t blk = (((size_t)e * NB + nt) * (Kdim / 32) + kb) * 2048;
#pragma unroll
    for (int ki = 0; ki < 2; ki++) {
        const int k0 = ki * 16 + 2 * tig;
        float2 w0 = *(const float2*)&src[k0];
        float2 w1 = *(const float2*)&src[k0 + 8];
        uint2 hi, lo;
        bsplit2(w0.x, w0.y, hi.x, lo.x);     /* b0: k=2tig,2tig+1   */
        bsplit2(w1.x, w1.y, hi.y, lo.y);     /* b1: k=2tig+8,2tig+9 */
        const size_t base = blk + ((size_t)(ki * 16 + ni) * 32 + lane) * 2;
        *(uint2*)&Gh[base] = hi;
        *(uint2*)&Gl[base] = lo;
    }
}

/* ---------------- stage loader: 48KB via cp.async (12 x 16B per thread) ---- */
__device__ __forceinline__ void stage_load(
    unsigned* smbuf, int st,
    const unsigned* __restrict__ Ah, const unsigned* __restrict__ Al,
    const unsigned* __restrict__ Bh, const unsigned* __restrict__ Bl,
    size_t ablk, size_t bblk, int tid)
{
    unsigned d = smem_u32(smbuf + st * STAGE_UINTS) + tid * 16;
    const unsigned* a_h = Ah + ablk * 4096 + tid * 4;
    const unsigned* a_l = Al + ablk * 4096 + tid * 4;
    const unsigned* b_h = Bh + bblk * 2048 + tid * 4;
    const unsigned* b_l = Bl + bblk * 2048 + tid * 4;
#pragma unroll
    for (int i = 0; i < 4; i++) CP16(d + i * 4096, a_h + i * 1024);
#pragma unroll
    for (int i = 0; i < 4; i++) CP16(d + 16384 + i * 4096, a_l + i * 1024);
#pragma unroll
    for (int i = 0; i < 2; i++) CP16(d + 32768 + i * 4096, b_h + i * 1024);
#pragma unroll
    for (int i = 0; i < 2; i++) CP16(d + 40960 + i * 4096, b_l + i * 1024);
    CP_COMMIT();
}

/* ---------------- GEMM mainloop (CTA 256x128, Kblk 32, 4 stages) ----------- */
__device__ __forceinline__ void gemm_loop(
    unsigned* smbuf,
    const unsigned* __restrict__ Ah, const unsigned* __restrict__ Al,
    const unsigned* __restrict__ Bh, const unsigned* __restrict__ Bl,
    size_t ablk0, size_t bblk0, int KB,
    float acc[4][8][4], int tid)
{
    const int lane = tid & 31, wid = tid >> 5;
    const int wm = wid >> 1, wn = wid & 1;

#pragma unroll
    for (int s = 0; s < 3; s++)
        stage_load(smbuf, s, Ah, Al, Bh, Bl, ablk0 + s, bblk0 + s, tid);

    for (int kb = 0; kb < KB; kb++) {
        const int st = kb & 3;
        if (kb + 3 < KB) {
            stage_load(smbuf, (kb + 3) & 3, Ah, Al, Bh, Bl,
                       ablk0 + kb + 3, bblk0 + kb + 3, tid);
            asm volatile("cp.async.wait_group 3;" ::: "memory");
        } else {
            asm volatile("cp.async.wait_group 0;" ::: "memory");
        }
        __syncthreads();
        const unsigned* sA = smbuf + st * STAGE_UINTS;
        const unsigned* sB = sA + 8192;
#pragma unroll
        for (int ki = 0; ki < 2; ki++) {
            const unsigned* pa = sA + ((ki * 16 + wm * 4) * 32 + lane) * 4;
            const unsigned* pb = sB + ((ki * 16 + wn * 8) * 32 + lane) * 2;
            uint4 ah[4];
            uint2 bh[8];
#pragma unroll
            for (int i = 0; i < 4; i++) ah[i] = *(const uint4*)(pa + i * 128);
#pragma unroll
            for (int j = 0; j < 8; j++) bh[j] = *(const uint2*)(pb + j * 64);
#pragma unroll
            for (int i = 0; i < 4; i++)
#pragma unroll
                for (int j = 0; j < 8; j++) mma16816(acc[i][j], ah[i], bh[j]);
            uint2 bl[8];
#pragma unroll
            for (int j = 0; j < 8; j++) bl[j] = *(const uint2*)(pb + 2048 + j * 64);
#pragma unroll
            for (int i = 0; i < 4; i++)
#pragma unroll
                for (int j = 0; j < 8; j++) mma16816(acc[i][j], ah[i], bl[j]);
            uint4 al[4];
#pragma unroll
            for (int i = 0; i < 4; i++) al[i] = *(const uint4*)(pa + 4096 + i * 128);
#pragma unroll
            for (int i = 0; i < 4; i++)
#pragma unroll
                for (int j = 0; j < 8; j++) mma16816(acc[i][j], al[i], bh[j]);
        }
        __syncthreads();
    }
}

__device__ __forceinline__ int resolve_expert(int p0) {
    int e = -1;
    if (p0 < g_segbase[NE]) {
#pragma unroll
        for (int i = NE - 1; i >= 0; i--)
            if (p0 >= g_segbase[i]) { e = i; break; }
    }
    return e;
}

/* ---------------- GEMM1: h = relu(X W1^T + b1) -> split A-layout ----------- */
__global__ __launch_bounds__(256, 1)
void k_gemm1(const float* __restrict__ b1) {
    __shared__ int s_e;
    extern __shared__ unsigned smbuf[];
    const int tid = threadIdx.x;
    const int nt = blockIdx.x, mt = blockIdx.y;

    if (tid == 0) s_e = resolve_expert(mt * 256);
    __syncthreads();
    const int e = s_e;
    if (e < 0) return;

    float acc[4][8][4];
#pragma unroll
    for (int i = 0; i < 4; i++)
#pragma unroll
        for (int j = 0; j < 8; j++)
#pragma unroll
            for (int c = 0; c < 4; c++) acc[i][j][c] = 0.f;

    gemm_loop(smbuf, g_xh, g_xl, g_w1h, g_w1l,
              (size_t)mt * KB1, ((size_t)e * NT1 + nt) * KB1, KB1, acc, tid);

    /* epilogue: bias+relu, bf16 split, write h in A-layout */
    const int lane = tid & 31, wid = tid >> 5;
    const int wm = wid >> 1, wn = wid & 1;
    const int tig = lane & 3;
    const float* bias = b1 + (size_t)e * HDIM + nt * 128 + wn * 64 + 2 * tig;
#pragma unroll
    for (int mi = 0; mi < 4; mi++) {
        const int mig = wm * 4 + mi;
#pragma unroll
        for (int jp = 0; jp < 4; jp++) {
            float2 b0 = *(const float2*)(bias + (2 * jp) * 8);
            float2 b1v = *(const float2*)(bias + (2 * jp + 1) * 8);
            const float* c0 = acc[mi][2 * jp];
            const float* c1 = acc[mi][2 * jp + 1];
            float v00 = fmaxf(c0[0] + b0.x, 0.f), v01 = fmaxf(c0[1] + b0.y, 0.f);
            float v02 = fmaxf(c0[2] + b0.x, 0.f), v03 = fmaxf(c0[3] + b0.y, 0.f);
            float v10 = fmaxf(c1[0] + b1v.x, 0.f), v11 = fmaxf(c1[1] + b1v.y, 0.f);
            float v12 = fmaxf(c1[2] + b1v.x, 0.f), v13 = fmaxf(c1[3] + b1v.y, 0.f);
            uint4 hi, lo;
            bsplit2(v00, v01, hi.x, lo.x);
            bsplit2(v02, v03, hi.y, lo.y);
            bsplit2(v10, v11, hi.z, lo.z);
            bsplit2(v12, v13, hi.w, lo.w);
            const int hcol0 = nt * 128 + wn * 64 + jp * 16;
            const size_t base = ((size_t)mt * KB2 + (hcol0 >> 5)) * 4096
                + ((size_t)(((hcol0 >> 4) & 1) * 16 + mig) * 32 + lane) * 4;
            *(uint4*)&g_hh[base] = hi;
            *(uint4*)&g_hl[base] = lo;
        }
    }
}

/* ---------------- GEMM2: out += w * (h W2^T + b2) -------------------------- */
__global__ __launch_bounds__(256, 1)
void k_gemm2(const float* __restrict__ b2, float* __restrict__ out) {
    __shared__ int s_e;
    __shared__ int stok[256];
    __shared__ float swgt[256];
    extern __shared__ unsigned smbuf[];
    const int tid = threadIdx.x;
    const int nt = blockIdx.x, mt = blockIdx.y;

    if (tid == 0) s_e = resolve_expert(mt * 256);
    __syncthreads();
    const int e = s_e;
    if (e < 0) return;

    stok[tid] = g_tok[mt * 256 + tid];
    swgt[tid] = g_wgt[mt * 256 + tid];

    float acc[4][8][4];
#pragma unroll
    for (int i = 0; i < 4; i++)
#pragma unroll
        for (int j = 0; j < 8; j++)
#pragma unroll
            for (int c = 0; c < 4; c++) acc[i][j][c] = 0.f;

    gemm_loop(smbuf, g_hh, g_hl, g_w2h, g_w2l,
              (size_t)mt * KB2, ((size_t)e * NT2 + nt) * KB2, KB2, acc, tid);

    const int lane = tid & 31, wid = tid >> 5;
    const int wm = wid >> 1, wn = wid & 1;
    const int g = lane >> 2, tig = lane & 3;
#pragma unroll
    for (int mi = 0; mi < 4; mi++) {
        const int r0 = wm * 64 + mi * 16 + g;
        const int t0 = stok[r0], t1 = stok[r0 + 8];
        const float w0 = swgt[r0], w1 = swgt[r0 + 8];
#pragma unroll
        for (int j = 0; j < 8; j++) {
            const int col = nt * 128 + wn * 64 + j * 8 + 2 * tig;
            float2 bb = *(const float2*)&b2[(size_t)e * DOUT + col];
            if (t0 >= 0) {
                float* d = out + (size_t)t0 * DOUT + col;
                atomicAdd(d,     w0 * (acc[mi][j][0] + bb.x));
                atomicAdd(d + 1, w0 * (acc[mi][j][1] + bb.y));
            }
            if (t1 >= 0) {
                float* d = out + (size_t)t1 * DOUT + col;
                atomicAdd(d,     w1 * (acc[mi][j][2] + bb.x));
                atomicAdd(d + 1, w1 * (acc[mi][j][3] + bb.y));
            }
        }
    }
}

/* ---------------- launch ---------------------------------------------------- */
extern "C" void kernel_launch(void* const* d_in, const int* in_sizes, int n_in,
                              void* d_out, int out_size) {
    const float* x  = (const float*)d_in[0];
    const float* rW = (const float*)d_in[1];
    const float* rb = (const float*)d_in[2];
    const float* W1 = (const float*)d_in[3];
    const float* b1 = (const float*)d_in[4];
    const float* W2 = (const float*)d_in[5];
    const float* b2 = (const float*)d_in[6];
    float* out = (float*)d_out;

    float* probs;
    if (out_size >= (int)(BQ * DOUT + BQ * NE)) {
        probs = out + (size_t)BQ * DOUT;
    } else {
        void* p = nullptr;
        cudaGetSymbolAddress(&p, g_probs_scratch);
        probs = (float*)p;
    }

    /* CRITICAL: resolve device addresses of scratch passed as kernel args.
       Passing the __device__ symbol directly from host code passes the HOST
       shadow address (silently writable via ATS on GB300!). */
    void *p_w1h = nullptr, *p_w1l = nullptr, *p_w2h = nullptr, *p_w2l = nullptr;
    cudaGetSymbolAddress(&p_w1h, g_w1h);
    cudaGetSymbolAddress(&p_w1l, g_w1l);
    cudaGetSymbolAddress(&p_w2h, g_w2h);
    cudaGetSymbolAddress(&p_w2l, g_w2l);

    cudaFuncSetAttribute(k_gemm1, cudaFuncAttributeMaxDynamicSharedMemorySize, DSMEM_BYTES);
    cudaFuncSetAttribute(k_gemm2, cudaFuncAttributeMaxDynamicSharedMemorySize, DSMEM_BYTES);

    k_zero_out<<<16384, 256>>>(out);
    k_init<<<1, 256>>>();
    k_router<<<BQ, 128>>>(x, rW, rb, probs);
    k_prefix<<<1, 1>>>();
    k_scatter<<<NA / 256, 256>>>();
    k_xsplit<<<dim3(KB1, MT), 512>>>(x);
    k_wsplit<<<dim3(KB1, NT1, NE), 512>>>(W1, (unsigned*)p_w1h, (unsigned*)p_w1l, DIN);
    k_wsplit<<<dim3(KB2, NT2, NE), 512>>>(W2, (unsigned*)p_w2h, (unsigned*)p_w2l, HDIM);
    k_gemm1<<<dim3(NT1, MT), 256, DSMEM_BYTES>>>(b1);
    k_gemm2<<<dim3(NT2, MT), 256, DSMEM_BYTES>>>(b2, out);
    (void)in_sizes; (void)n_in;
}